// round 3
// baseline (speedup 1.0000x reference)
#include <cuda_runtime.h>
#include <cuda_bf16.h>
#include <stdint.h>

#define BSZ   8
#define LEN   2048
#define HIDN  1024
#define NHD   16
#define HDIM  64
#define M_TOT (BSZ * LEN)

__device__ float g_V1[(size_t)M_TOT * (NHD * HDIM)];
__device__ float g_dots[M_TOT * NHD];
__device__ int2  g_fmap[M_TOT * NHD];
__device__ int2  g_bmap[M_TOT * NHD];

// ---------------- GEMM (TF32 mma), fused relu + K-dot epilogue ----------------
#define BM 128
#define BN 128
#define BKK 16
#define A_STRIDE 20
#define B_STRIDE 136
#define A_STAGE (BM * A_STRIDE)
#define B_STAGE (BKK * B_STRIDE)
#define GEMM_SMEM_BYTES (2 * (A_STAGE + B_STAGE) * 4)

__device__ __forceinline__ void cp_async16(uint32_t saddr, const void* gptr) {
    asm volatile("cp.async.ca.shared.global [%0], [%1], 16;\n" :: "r"(saddr), "l"(gptr));
}
__device__ __forceinline__ void cp_commit() { asm volatile("cp.async.commit_group;\n"); }
__device__ __forceinline__ void cp_wait0() { asm volatile("cp.async.wait_group 0;\n"); }

__device__ __forceinline__ uint32_t f2tf32(float x) {
    uint32_t r; asm("cvt.rna.tf32.f32 %0, %1;" : "=r"(r) : "f"(x)); return r;
}
__device__ __forceinline__ void mma_tf32(float* d, const uint32_t* a, const uint32_t* b) {
    asm volatile("mma.sync.aligned.m16n8k8.row.col.f32.tf32.tf32.f32 "
        "{%0,%1,%2,%3},{%4,%5,%6,%7},{%8,%9},{%0,%1,%2,%3};\n"
        : "+f"(d[0]), "+f"(d[1]), "+f"(d[2]), "+f"(d[3])
        : "r"(a[0]), "r"(a[1]), "r"(a[2]), "r"(a[3]), "r"(b[0]), "r"(b[1]));
}

__device__ __forceinline__ void load_stage(
    const float* __restrict__ X, const float* __restrict__ Wb,
    int m0, int wcol0, int kt, int st, uint32_t a_base, uint32_t b_base, int tid)
{
    #pragma unroll
    for (int i = 0; i < 2; i++) {
        int c = tid + i * 256, row = c >> 2, q = c & 3;
        cp_async16(a_base + (uint32_t)((st * A_STAGE + row * A_STRIDE + (q << 2)) << 2),
                   X + ((size_t)(m0 + row) << 10) + kt * BKK + (q << 2));
    }
    #pragma unroll
    for (int i = 0; i < 2; i++) {
        int c = tid + i * 256, row = c >> 5, q = c & 31;
        cp_async16(b_base + (uint32_t)((st * B_STAGE + row * B_STRIDE + (q << 2)) << 2),
                   Wb + ((size_t)(kt * BKK + row) << 10) + wcol0 + (q << 2));
    }
}

__global__ __launch_bounds__(256) void gemm_kernel(
    const float* __restrict__ X,
    const float* __restrict__ Kw, const float* __restrict__ Kb,
    const float* __restrict__ Vw, const float* __restrict__ Vb,
    const float* __restrict__ RH)
{
    extern __shared__ float smem[];
    float* As = smem;
    float* Bs = smem + 2 * A_STAGE;
    uint32_t a_base = (uint32_t)__cvta_generic_to_shared(As);
    uint32_t b_base = (uint32_t)__cvta_generic_to_shared(Bs);

    const int tid = threadIdx.x;
    const int m0 = blockIdx.y * BM;
    const int j0 = blockIdx.x * BN;
    const bool isK = (j0 < 1024);
    const float* Wb = isK ? Kw : Vw;
    const int wcol0 = isK ? j0 : (j0 - 1024);

    const int warp = tid >> 5, lane = tid & 31;
    const int g = lane >> 2, tg = lane & 3;
    const int wm = warp & 3, wn = warp >> 2;

    float acc[2][8][4];
    #pragma unroll
    for (int a = 0; a < 2; a++)
        #pragma unroll
        for (int b = 0; b < 8; b++)
            #pragma unroll
            for (int c = 0; c < 4; c++) acc[a][b][c] = 0.f;

    load_stage(X, Wb, m0, wcol0, 0, 0, a_base, b_base, tid);
    cp_commit();

    const int KT = HIDN / BKK;
    for (int kt = 0; kt < KT; kt++) {
        cp_wait0();
        __syncthreads();
        if (kt + 1 < KT)
            load_stage(X, Wb, m0, wcol0, kt + 1, (kt + 1) & 1, a_base, b_base, tid);
        cp_commit();
        const int st = kt & 1;
        const float* Asb = As + st * A_STAGE;
        const float* Bsb = Bs + st * B_STAGE;
        #pragma unroll
        for (int ks = 0; ks < 2; ks++) {
            uint32_t af[2][4];
            #pragma unroll
            for (int mt = 0; mt < 2; mt++) {
                int r = wm * 32 + mt * 16 + g;
                int k = ks * 8 + tg;
                af[mt][0] = f2tf32(Asb[r * A_STRIDE + k]);
                af[mt][1] = f2tf32(Asb[(r + 8) * A_STRIDE + k]);
                af[mt][2] = f2tf32(Asb[r * A_STRIDE + k + 4]);
                af[mt][3] = f2tf32(Asb[(r + 8) * A_STRIDE + k + 4]);
            }
            #pragma unroll
            for (int nt = 0; nt < 8; nt++) {
                int n = wn * 64 + nt * 8 + g;
                int k = ks * 8 + tg;
                uint32_t bf[2];
                bf[0] = f2tf32(Bsb[k * B_STRIDE + n]);
                bf[1] = f2tf32(Bsb[(k + 4) * B_STRIDE + n]);
                mma_tf32(acc[0][nt], af[0], bf);
                mma_tf32(acc[1][nt], af[1], bf);
            }
        }
    }

    if (isK) {
        const int head = (j0 >> 6) + wn;
        const float* rh = RH + head * HDIM;
        float dotp[4] = {0.f, 0.f, 0.f, 0.f};
        #pragma unroll
        for (int mt = 0; mt < 2; mt++) {
            #pragma unroll
            for (int nt = 0; nt < 8; nt++) {
                int ch = nt * 8 + 2 * tg;
                int jc = j0 + wn * 64 + ch;
                float b0 = Kb[jc], b1 = Kb[jc + 1];
                float w0 = rh[ch], w1 = rh[ch + 1];
                float v;
                v = fmaxf(acc[mt][nt][0] + b0, 0.f); dotp[mt * 2 + 0] += v * w0;
                v = fmaxf(acc[mt][nt][1] + b1, 0.f); dotp[mt * 2 + 0] += v * w1;
                v = fmaxf(acc[mt][nt][2] + b0, 0.f); dotp[mt * 2 + 1] += v * w0;
                v = fmaxf(acc[mt][nt][3] + b1, 0.f); dotp[mt * 2 + 1] += v * w1;
            }
        }
        #pragma unroll
        for (int i = 0; i < 4; i++) {
            dotp[i] += __shfl_xor_sync(0xffffffffu, dotp[i], 1);
            dotp[i] += __shfl_xor_sync(0xffffffffu, dotp[i], 2);
        }
        if (tg == 0) {
            #pragma unroll
            for (int mt = 0; mt < 2; mt++) {
                int r = m0 + wm * 32 + mt * 16 + g;
                g_dots[r * NHD + head] = dotp[mt * 2 + 0];
                g_dots[(r + 8) * NHD + head] = dotp[mt * 2 + 1];
            }
        }
    } else {
        #pragma unroll
        for (int mt = 0; mt < 2; mt++) {
            #pragma unroll
            for (int nt = 0; nt < 8; nt++) {
                int jv = (j0 - 1024) + wn * 64 + nt * 8 + 2 * tg;
                float b0 = Vb[jv], b1 = Vb[jv + 1];
                int r = m0 + wm * 32 + mt * 16 + g;
                float2 s0, s1;
                s0.x = fmaxf(acc[mt][nt][0] + b0, 0.f);
                s0.y = fmaxf(acc[mt][nt][1] + b1, 0.f);
                s1.x = fmaxf(acc[mt][nt][2] + b0, 0.f);
                s1.y = fmaxf(acc[mt][nt][3] + b1, 0.f);
                *(float2*)&g_V1[(size_t)r * 1024 + jv] = s0;
                *(float2*)&g_V1[(size_t)(r + 8) * 1024 + jv] = s1;
            }
        }
    }
}

// ---------------- fp64 fixup of near-threshold dots ----------------
#define FIX_TAU 4e-3f

__global__ __launch_bounds__(256) void fixup_kernel(
    const float* __restrict__ X, const float* __restrict__ Kw,
    const float* __restrict__ Kb, const float* __restrict__ RH)
{
    __shared__ int s_cnt;
    __shared__ int s_ids[256];
    __shared__ double s_red[256];
    __shared__ double s_val[64];

    const int tid = threadIdx.x;
    if (tid == 0) s_cnt = 0;
    __syncthreads();

    int id = blockIdx.x * 256 + tid;
    float d = g_dots[id];
    if (fabsf(d - 0.5f) < FIX_TAU) {
        int p = atomicAdd(&s_cnt, 1);
        s_ids[p] = id;
    }
    __syncthreads();
    const int cnt = s_cnt;

    for (int i = 0; i < cnt; i++) {
        const int t = s_ids[i];
        const int m = t >> 4, n = t & 15;
        const int h = tid & 63, part = tid >> 6;
        const float* xr = X + ((size_t)m << 10);
        const float* wc = Kw + n * 64 + h;
        double ps = 0.0;
        const int k0 = part * 256;
        for (int k = 0; k < 256; k++)
            ps += (double)xr[k0 + k] * (double)wc[(size_t)(k0 + k) << 10];
        s_red[tid] = ps;
        __syncthreads();
        if (tid < 64) {
            double pre = s_red[tid] + s_red[tid + 64] + s_red[tid + 128] + s_red[tid + 192]
                       + (double)Kb[n * 64 + tid];
            double r = pre > 0.0 ? pre : 0.0;
            s_val[tid] = r * (double)RH[n * 64 + tid];
        }
        __syncthreads();
        if (tid == 0) {
            double s = 0.0;
            for (int h2 = 0; h2 < 64; h2++) s += s_val[h2];
            g_dots[t] = (float)s;
        }
        __syncthreads();
    }
}

// ---------------- warp-segmented nearest-valid scan ----------------
struct Seg { int cnt, v1, v2; };

__device__ __forceinline__ Seg seg_combine(const Seg& prev, const Seg& cur) {
    Seg r;
    if (cur.cnt >= 2) r = cur;
    else if (cur.cnt == 1) { r.cnt = min(prev.cnt + 1, 2); r.v1 = cur.v1; r.v2 = prev.v1; }
    else r = prev;
    return r;
}

__global__ void scan_kernel()
{
    const int bidx = blockIdx.x >> 4;
    const int n = blockIdx.x & 15;
    const int lane = threadIdx.x;
    const int base_l = lane * 64;

    const float* dp = g_dots + ((size_t)bidx * LEN) * NHD + n;
    unsigned long long bits = 0ull;
    for (int j = 0; j < 64; j++)
        if (__ldg(&dp[(size_t)(base_l + j) * NHD]) > 0.5f) bits |= (1ull << j);

    { // forward: ignore pos 0, defaults 0
        unsigned long long fb = bits;
        if (lane == 0) fb &= ~1ull;
        Seg s; s.cnt = 0; s.v1 = 0; s.v2 = 0;
        for (int j = 0; j < 64; j++)
            if ((fb >> j) & 1ull) { s.v2 = s.v1; s.v1 = base_l + j; s.cnt = min(s.cnt + 1, 2); }
        Seg inc = s;
        for (int d = 1; d < 32; d <<= 1) {
            Seg o;
            o.cnt = __shfl_up_sync(0xffffffffu, inc.cnt, d);
            o.v1  = __shfl_up_sync(0xffffffffu, inc.v1, d);
            o.v2  = __shfl_up_sync(0xffffffffu, inc.v2, d);
            if (lane >= d) inc = seg_combine(o, inc);
        }
        Seg ex;
        ex.cnt = __shfl_up_sync(0xffffffffu, inc.cnt, 1);
        ex.v1  = __shfl_up_sync(0xffffffffu, inc.v1, 1);
        ex.v2  = __shfl_up_sync(0xffffffffu, inc.v2, 1);
        if (lane == 0) { ex.cnt = 0; ex.v1 = 0; ex.v2 = 0; }
        int a = (ex.cnt >= 1) ? ex.v1 : 0;
        int b = (ex.cnt >= 2) ? ex.v2 : 0;
        int2* out = g_fmap + ((size_t)bidx * LEN) * NHD + n;
        for (int j = 0; j < 64; j++) {
            int p = base_l + j;
            if ((fb >> j) & 1ull) { b = a; a = p; }
            out[(size_t)p * NHD] = make_int2(a, b);
        }
    }

    { // backward: ignore pos L-1, store mirrored index, defaults L-1
        unsigned long long bb = bits;
        if (lane == 31) bb &= ~(1ull << 63);
        Seg s; s.cnt = 0; s.v1 = LEN - 1; s.v2 = LEN - 1;
        for (int j = 63; j >= 0; j--)
            if ((bb >> j) & 1ull) { s.v2 = s.v1; s.v1 = (LEN - 1) - (base_l + j); s.cnt = min(s.cnt + 1, 2); }
        Seg inc = s;
        for (int d = 1; d < 32; d <<= 1) {
            Seg o;
            o.cnt = __shfl_down_sync(0xffffffffu, inc.cnt, d);
            o.v1  = __shfl_down_sync(0xffffffffu, inc.v1, d);
            o.v2  = __shfl_down_sync(0xffffffffu, inc.v2, d);
            if (lane + d < 32) inc = seg_combine(o, inc);
        }
        Seg ex;
        ex.cnt = __shfl_down_sync(0xffffffffu, inc.cnt, 1);
        ex.v1  = __shfl_down_sync(0xffffffffu, inc.v1, 1);
        ex.v2  = __shfl_down_sync(0xffffffffu, inc.v2, 1);
        if (lane == 31) { ex.cnt = 0; ex.v1 = LEN - 1; ex.v2 = LEN - 1; }
        int a = (ex.cnt >= 1) ? ex.v1 : (LEN - 1);
        int b = (ex.cnt >= 2) ? ex.v2 : (LEN - 1);
        int2* out = g_bmap + ((size_t)bidx * LEN) * NHD + n;
        for (int j = 63; j >= 0; j--) {
            int p = base_l + j;
            if ((bb >> j) & 1ull) { b = a; a = (LEN - 1) - p; }
            out[(size_t)p * NHD] = make_int2(a, b);
        }
    }
}

// ---------------- weighted gather ----------------
__global__ __launch_bounds__(256) void gather_kernel(
    const float* __restrict__ Bw, float* __restrict__ out)
{
    int gid = blockIdx.x * 16 + (threadIdx.x >> 4);
    int q = threadIdx.x & 15;
    int n = gid & 15;
    int bl = gid >> 4;
    int b = bl >> 11;
    int2 fm = g_fmap[(size_t)bl * NHD + n];
    int2 bm = g_bmap[(size_t)bl * NHD + n];
    const float* vbase = g_V1 + (((size_t)b << 11) << 10);
    size_t coff = (size_t)n * 64 + q * 4;
    float4 v0 = *(const float4*)(vbase + ((size_t)fm.x << 10) + coff);
    float4 v1 = *(const float4*)(vbase + ((size_t)fm.y << 10) + coff);
    float4 v2 = *(const float4*)(vbase + ((size_t)bm.x << 10) + coff);
    float4 v3 = *(const float4*)(vbase + ((size_t)bm.y << 10) + coff);
    float w0 = Bw[n * 4 + 0], w1 = Bw[n * 4 + 1], w2 = Bw[n * 4 + 2], w3 = Bw[n * 4 + 3];
    float4 r;
    r.x = w0 * v0.x + w1 * v1.x + w2 * v2.x + w3 * v3.x;
    r.y = w0 * v0.y + w1 * v1.y + w2 * v2.y + w3 * v3.y;
    r.z = w0 * v0.z + w1 * v1.z + w2 * v2.z + w3 * v3.z;
    r.w = w0 * v0.w + w1 * v1.w + w2 * v2.w + w3 * v3.w;
    *(float4*)(out + (size_t)bl * 1024 + coff) = r;
}

// ---------------- launch ----------------
extern "C" void kernel_launch(void* const* d_in, const int* in_sizes, int n_in,
                              void* d_out, int out_size)
{
    const float* X  = (const float*)d_in[0];
    const float* Kw = (const float*)d_in[1];
    const float* Kb = (const float*)d_in[2];
    const float* Vw = (const float*)d_in[3];
    const float* Vb = (const float*)d_in[4];
    const float* Bw = (const float*)d_in[5];
    const float* RH = (const float*)d_in[6];
    float* out = (float*)d_out;

    gemm_kernel<<<dim3(16, 128), 256, GEMM_SMEM_BYTES>>>(X, Kw, Kb, Vw, Vb, RH);
    fixup_kernel<<<M_TOT * NHD / 256, 256>>>(X, Kw, Kb, RH);
    scan_kernel<<<BSZ * NHD, 32>>>();
    gather_kernel<<<M_TOT * NHD / 16, 256>>>(Bw, out);
}

// round 10
// speedup vs baseline: 1.2743x; 1.2743x over previous
#include <cuda_runtime.h>
#include <cuda_fp16.h>
#include <cuda_bf16.h>
#include <stdint.h>

#define BSZ   8
#define LEN   2048
#define HIDN  1024
#define NHD   16
#define HDIM  64
#define M_TOT (BSZ * LEN)

__device__ float  g_V1[(size_t)M_TOT * (NHD * HDIM)];
__device__ __half g_Xh[(size_t)M_TOT * HIDN];
__device__ __half g_WTh[(size_t)2048 * HIDN];   // [n][k] fp16 transposed weights
__device__ float  g_dots[M_TOT * NHD];
__device__ int2   g_fmap[M_TOT * NHD];
__device__ int2   g_bmap[M_TOT * NHD];

// ---------------- helpers ----------------
__device__ __forceinline__ uint32_t smem_u32(const void* p) {
    return (uint32_t)__cvta_generic_to_shared(p);
}
__device__ __forceinline__ void cp_async16(uint32_t saddr, const void* gptr) {
    asm volatile("cp.async.ca.shared.global [%0], [%1], 16;\n" :: "r"(saddr), "l"(gptr));
}
__device__ __forceinline__ void cp_commit() { asm volatile("cp.async.commit_group;\n"); }
__device__ __forceinline__ void cp_wait1() { asm volatile("cp.async.wait_group 1;\n"); }

__device__ __forceinline__ void ldsm4(uint32_t* r, uint32_t addr) {
    asm volatile("ldmatrix.sync.aligned.m8n8.x4.shared.b16 {%0,%1,%2,%3}, [%4];"
        : "=r"(r[0]), "=r"(r[1]), "=r"(r[2]), "=r"(r[3]) : "r"(addr));
}
__device__ __forceinline__ void mma_f16(float* d, const uint32_t* a, const uint32_t* b) {
    asm volatile("mma.sync.aligned.m16n8k16.row.col.f32.f16.f16.f32 "
        "{%0,%1,%2,%3},{%4,%5,%6,%7},{%8,%9},{%0,%1,%2,%3};\n"
        : "+f"(d[0]), "+f"(d[1]), "+f"(d[2]), "+f"(d[3])
        : "r"(a[0]), "r"(a[1]), "r"(a[2]), "r"(a[3]), "r"(b[0]), "r"(b[1]));
}

// ---------------- pre-pass: X -> fp16 ----------------
__global__ __launch_bounds__(256) void conv_x(const float* __restrict__ X)
{
    size_t i = ((size_t)blockIdx.x * 256 + threadIdx.x) * 8;
    float4 v0 = *(const float4*)(X + i);
    float4 v1 = *(const float4*)(X + i + 4);
    __half2 h0 = __floats2half2_rn(v0.x, v0.y);
    __half2 h1 = __floats2half2_rn(v0.z, v0.w);
    __half2 h2 = __floats2half2_rn(v1.x, v1.y);
    __half2 h3 = __floats2half2_rn(v1.z, v1.w);
    uint4 o;
    o.x = *(uint32_t*)&h0; o.y = *(uint32_t*)&h1;
    o.z = *(uint32_t*)&h2; o.w = *(uint32_t*)&h3;
    *(uint4*)(g_Xh + i) = o;
}

// ---------------- pre-pass: W transpose -> fp16 [n][k] ----------------
__global__ __launch_bounds__(256) void transpose_w(
    const float* __restrict__ Kw, const float* __restrict__ Vw)
{
    __shared__ float t[32][33];
    const int n0 = blockIdx.x * 32, k0 = blockIdx.y * 32;
    const float* W = (n0 < 1024) ? Kw : Vw;
    const int nb = n0 & 1023;
    const int tx = threadIdx.x, ty = threadIdx.y;
    #pragma unroll
    for (int r = ty; r < 32; r += 8)
        t[r][tx] = W[(size_t)(k0 + r) * 1024 + nb + tx];
    __syncthreads();
    #pragma unroll
    for (int r = ty; r < 32; r += 8)
        g_WTh[(size_t)(n0 + r) * 1024 + k0 + tx] = __float2half_rn(t[tx][r]);
}

// ---------------- fp16 mma GEMM, fused relu + bias + K-dot epilogue ----------
#define AROW 80                       // bytes per padded smem row (64B data)
#define TILE_B (128 * AROW)           // 10240
#define STG 3
#define GEMM_SMEM (2 * STG * TILE_B)  // 61440

__device__ __forceinline__ void load_tiles_f16(int m0, int n0, int kt, int st, uint32_t sb, int tid)
{
    const int kk = kt * 32;
    const uint32_t sA = sb + st * TILE_B;
    const uint32_t sB = sb + (STG + st) * TILE_B;
    #pragma unroll
    for (int i = 0; i < 2; i++) {
        int c = tid + i * 256, row = c >> 2, q = c & 3;
        cp_async16(sA + (uint32_t)(row * AROW + q * 16),
                   g_Xh + (size_t)(m0 + row) * 1024 + kk + q * 8);
    }
    #pragma unroll
    for (int i = 0; i < 2; i++) {
        int c = tid + i * 256, row = c >> 2, q = c & 3;
        cp_async16(sB + (uint32_t)(row * AROW + q * 16),
                   g_WTh + (size_t)(n0 + row) * 1024 + kk + q * 8);
    }
}

__global__ __launch_bounds__(256) void gemm_f16(
    const float* __restrict__ Kb, const float* __restrict__ Vb,
    const float* __restrict__ RH)
{
    extern __shared__ char smem[];
    const uint32_t sb = smem_u32(smem);
    const int tid = threadIdx.x, wid = tid >> 5, lane = tid & 31;
    const int wm = wid & 3, wn = wid >> 2;
    const int m0 = blockIdx.y * 128;
    const int j0 = blockIdx.x * 128;
    const int n0 = j0;                 // columns in g_WTh space (0..2047)

    float acc[2][8][4];
    #pragma unroll
    for (int a = 0; a < 2; a++)
        #pragma unroll
        for (int b = 0; b < 8; b++)
            #pragma unroll
            for (int c = 0; c < 4; c++) acc[a][b][c] = 0.f;

    load_tiles_f16(m0, n0, 0, 0, sb, tid); cp_commit();
    load_tiles_f16(m0, n0, 1, 1, sb, tid); cp_commit();

    const int j = lane >> 3, r = lane & 7;
    const int KT = 32;
    for (int kt = 0; kt < KT; kt++) {
        cp_wait1();
        __syncthreads();
        if (kt + 2 < KT) load_tiles_f16(m0, n0, kt + 2, (kt + 2) % STG, sb, tid);
        cp_commit();

        const int st = kt % STG;
        const uint32_t sA = sb + st * TILE_B;
        const uint32_t sB = sb + (STG + st) * TILE_B;
        #pragma unroll
        for (int kh = 0; kh < 2; kh++) {
            uint32_t a0[4], a1[4];
            const uint32_t arow = (uint32_t)(wm * 32 + ((j & 1) << 3) + r);
            const uint32_t acol = (uint32_t)((kh << 4) + ((j >> 1) << 3));
            ldsm4(a0, sA + arow * AROW + acol * 2);
            ldsm4(a1, sA + (arow + 16) * AROW + acol * 2);
            #pragma unroll
            for (int g2 = 0; g2 < 4; g2++) {
                uint32_t bm[4];
                const uint32_t brow = (uint32_t)(wn * 64 + (g2 << 4) + ((j >> 1) << 3) + r);
                const uint32_t bcol = (uint32_t)((kh << 4) + ((j & 1) << 3));
                ldsm4(bm, sB + brow * AROW + bcol * 2);
                mma_f16(acc[0][2 * g2],     a0, &bm[0]);
                mma_f16(acc[1][2 * g2],     a1, &bm[0]);
                mma_f16(acc[0][2 * g2 + 1], a0, &bm[2]);
                mma_f16(acc[1][2 * g2 + 1], a1, &bm[2]);
            }
        }
    }

    const int g = lane >> 2, tg = lane & 3;
    if (j0 < 1024) {
        const int head = (j0 >> 6) + wn;
        const float* rh = RH + head * HDIM;
        float dotp[4] = {0.f, 0.f, 0.f, 0.f};
        #pragma unroll
        for (int mt = 0; mt < 2; mt++) {
            #pragma unroll
            for (int nt = 0; nt < 8; nt++) {
                int ch = nt * 8 + 2 * tg;
                int jc = j0 + wn * 64 + ch;
                float b0 = Kb[jc], b1 = Kb[jc + 1];
                float w0 = rh[ch], w1 = rh[ch + 1];
                float v;
                v = fmaxf(acc[mt][nt][0] + b0, 0.f); dotp[mt * 2 + 0] += v * w0;
                v = fmaxf(acc[mt][nt][1] + b1, 0.f); dotp[mt * 2 + 0] += v * w1;
                v = fmaxf(acc[mt][nt][2] + b0, 0.f); dotp[mt * 2 + 1] += v * w0;
                v = fmaxf(acc[mt][nt][3] + b1, 0.f); dotp[mt * 2 + 1] += v * w1;
            }
        }
        #pragma unroll
        for (int i = 0; i < 4; i++) {
            dotp[i] += __shfl_xor_sync(0xffffffffu, dotp[i], 1);
            dotp[i] += __shfl_xor_sync(0xffffffffu, dotp[i], 2);
        }
        if (tg == 0) {
            #pragma unroll
            for (int mt = 0; mt < 2; mt++) {
                int rr = m0 + wm * 32 + mt * 16 + g;
                g_dots[rr * NHD + head] = dotp[mt * 2 + 0];
                g_dots[(rr + 8) * NHD + head] = dotp[mt * 2 + 1];
            }
        }
    } else {
        #pragma unroll
        for (int mt = 0; mt < 2; mt++) {
            #pragma unroll
            for (int nt = 0; nt < 8; nt++) {
                int jv = (j0 - 1024) + wn * 64 + nt * 8 + 2 * tg;
                float b0 = Vb[jv], b1 = Vb[jv + 1];
                int rr = m0 + wm * 32 + mt * 16 + g;
                float2 s0, s1;
                s0.x = fmaxf(acc[mt][nt][0] + b0, 0.f);
                s0.y = fmaxf(acc[mt][nt][1] + b1, 0.f);
                s1.x = fmaxf(acc[mt][nt][2] + b0, 0.f);
                s1.y = fmaxf(acc[mt][nt][3] + b1, 0.f);
                *(float2*)&g_V1[(size_t)rr * 1024 + jv] = s0;
                *(float2*)&g_V1[(size_t)(rr + 8) * 1024 + jv] = s1;
            }
        }
    }
}

// ---------------- fp64 fixup of near-threshold dots ----------------
#define FIX_TAU 4e-3f

__global__ __launch_bounds__(256) void fixup_kernel(
    const float* __restrict__ X, const float* __restrict__ Kw,
    const float* __restrict__ Kb, const float* __restrict__ RH)
{
    __shared__ int s_cnt;
    __shared__ int s_ids[256];
    __shared__ double s_red[256];
    __shared__ double s_val[64];

    const int tid = threadIdx.x;
    if (tid == 0) s_cnt = 0;
    __syncthreads();

    int id = blockIdx.x * 256 + tid;
    float d = g_dots[id];
    if (fabsf(d - 0.5f) < FIX_TAU) {
        int p = atomicAdd(&s_cnt, 1);
        s_ids[p] = id;
    }
    __syncthreads();
    const int cnt = s_cnt;

    for (int i = 0; i < cnt; i++) {
        const int t = s_ids[i];
        const int m = t >> 4, n = t & 15;
        const int part = tid >> 6;
        const int h = tid & 63;
        const float* xr = X + ((size_t)m << 10);
        const float* wc = Kw + n * 64 + h;
        double ps = 0.0;
        const int k0 = part * 256;
        for (int k = 0; k < 256; k++)
            ps += (double)xr[k0 + k] * (double)wc[(size_t)(k0 + k) << 10];
        s_red[tid] = ps;
        __syncthreads();
        if (tid < 64) {
            double pre = s_red[tid] + s_red[tid + 64] + s_red[tid + 128] + s_red[tid + 192]
                       + (double)Kb[n * 64 + tid];
            double r = pre > 0.0 ? pre : 0.0;
            s_val[tid] = r * (double)RH[n * 64 + tid];
        }
        __syncthreads();
        if (tid == 0) {
            double s = 0.0;
            for (int h2 = 0; h2 < 64; h2++) s += s_val[h2];
            g_dots[t] = (float)s;
        }
        __syncthreads();
    }
}

// ---------------- warp-segmented nearest-valid scan ----------------
struct Seg { int cnt, v1, v2; };

__device__ __forceinline__ Seg seg_combine(const Seg& prev, const Seg& cur) {
    Seg r;
    if (cur.cnt >= 2) r = cur;
    else if (cur.cnt == 1) { r.cnt = min(prev.cnt + 1, 2); r.v1 = cur.v1; r.v2 = prev.v1; }
    else r = prev;
    return r;
}

__global__ void scan_kernel()
{
    const int bidx = blockIdx.x >> 4;
    const int n = blockIdx.x & 15;
    const int lane = threadIdx.x;
    const int base_l = lane * 64;

    const float* dp = g_dots + ((size_t)bidx * LEN) * NHD + n;
    unsigned long long bits = 0ull;
    for (int j = 0; j < 64; j++)
        if (__ldg(&dp[(size_t)(base_l + j) * NHD]) > 0.5f) bits |= (1ull << j);

    { // forward: ignore pos 0, defaults 0
        unsigned long long fb = bits;
        if (lane == 0) fb &= ~1ull;
        Seg s; s.cnt = 0; s.v1 = 0; s.v2 = 0;
        for (int j = 0; j < 64; j++)
            if ((fb >> j) & 1ull) { s.v2 = s.v1; s.v1 = base_l + j; s.cnt = min(s.cnt + 1, 2); }
        Seg inc = s;
        for (int d = 1; d < 32; d <<= 1) {
            Seg o;
            o.cnt = __shfl_up_sync(0xffffffffu, inc.cnt, d);
            o.v1  = __shfl_up_sync(0xffffffffu, inc.v1, d);
            o.v2  = __shfl_up_sync(0xffffffffu, inc.v2, d);
            if (lane >= d) inc = seg_combine(o, inc);
        }
        Seg ex;
        ex.cnt = __shfl_up_sync(0xffffffffu, inc.cnt, 1);
        ex.v1  = __shfl_up_sync(0xffffffffu, inc.v1, 1);
        ex.v2  = __shfl_up_sync(0xffffffffu, inc.v2, 1);
        if (lane == 0) { ex.cnt = 0; ex.v1 = 0; ex.v2 = 0; }
        int a = (ex.cnt >= 1) ? ex.v1 : 0;
        int b = (ex.cnt >= 2) ? ex.v2 : 0;
        int2* out = g_fmap + ((size_t)bidx * LEN) * NHD + n;
        for (int j = 0; j < 64; j++) {
            int p = base_l + j;
            if ((fb >> j) & 1ull) { b = a; a = p; }
            out[(size_t)p * NHD] = make_int2(a, b);
        }
    }

    { // backward: ignore pos L-1, store mirrored index, defaults L-1
        unsigned long long bb = bits;
        if (lane == 31) bb &= ~(1ull << 63);
        Seg s; s.cnt = 0; s.v1 = LEN - 1; s.v2 = LEN - 1;
        for (int j = 63; j >= 0; j--)
            if ((bb >> j) & 1ull) { s.v2 = s.v1; s.v1 = (LEN - 1) - (base_l + j); s.cnt = min(s.cnt + 1, 2); }
        Seg inc = s;
        for (int d = 1; d < 32; d <<= 1) {
            Seg o;
            o.cnt = __shfl_down_sync(0xffffffffu, inc.cnt, d);
            o.v1  = __shfl_down_sync(0xffffffffu, inc.v1, d);
            o.v2  = __shfl_down_sync(0xffffffffu, inc.v2, d);
            if (lane + d < 32) inc = seg_combine(o, inc);
        }
        Seg ex;
        ex.cnt = __shfl_down_sync(0xffffffffu, inc.cnt, 1);
        ex.v1  = __shfl_down_sync(0xffffffffu, inc.v1, 1);
        ex.v2  = __shfl_down_sync(0xffffffffu, inc.v2, 1);
        if (lane == 31) { ex.cnt = 0; ex.v1 = LEN - 1; ex.v2 = LEN - 1; }
        int a = (ex.cnt >= 1) ? ex.v1 : (LEN - 1);
        int b = (ex.cnt >= 2) ? ex.v2 : (LEN - 1);
        int2* out = g_bmap + ((size_t)bidx * LEN) * NHD + n;
        for (int j = 63; j >= 0; j--) {
            int p = base_l + j;
            if ((bb >> j) & 1ull) { b = a; a = (LEN - 1) - p; }
            out[(size_t)p * NHD] = make_int2(a, b);
        }
    }
}

// ---------------- weighted gather ----------------
__global__ __launch_bounds__(256) void gather_kernel(
    const float* __restrict__ Bw, float* __restrict__ out)
{
    int gid = blockIdx.x * 16 + (threadIdx.x >> 4);
    int q = threadIdx.x & 15;
    int n = gid & 15;
    int bl = gid >> 4;
    int b = bl >> 11;
    int2 fm = g_fmap[(size_t)bl * NHD + n];
    int2 bm = g_bmap[(size_t)bl * NHD + n];
    const float* vbase = g_V1 + (((size_t)b << 11) << 10);
    size_t coff = (size_t)n * 64 + q * 4;
    float4 v0 = *(const float4*)(vbase + ((size_t)fm.x << 10) + coff);
    float4 v1 = *(const float4*)(vbase + ((size_t)fm.y << 10) + coff);
    float4 v2 = *(const float4*)(vbase + ((size_t)bm.x << 10) + coff);
    float4 v3 = *(const float4*)(vbase + ((size_t)bm.y << 10) + coff);
    float w0 = Bw[n * 4 + 0], w1 = Bw[n * 4 + 1], w2 = Bw[n * 4 + 2], w3 = Bw[n * 4 + 3];
    float4 r;
    r.x = w0 * v0.x + w1 * v1.x + w2 * v2.x + w3 * v3.x;
    r.y = w0 * v0.y + w1 * v1.y + w2 * v2.y + w3 * v3.y;
    r.z = w0 * v0.z + w1 * v1.z + w2 * v2.z + w3 * v3.z;
    r.w = w0 * v0.w + w1 * v1.w + w2 * v2.w + w3 * v3.w;
    *(float4*)(out + (size_t)bl * 1024 + coff) = r;
}

// ---------------- launch ----------------
extern "C" void kernel_launch(void* const* d_in, const int* in_sizes, int n_in,
                              void* d_out, int out_size)
{
    const float* X  = (const float*)d_in[0];
    const float* Kw = (const float*)d_in[1];
    const float* Kb = (const float*)d_in[2];
    const float* Vw = (const float*)d_in[3];
    const float* Vb = (const float*)d_in[4];
    const float* Bw = (const float*)d_in[5];
    const float* RH = (const float*)d_in[6];
    float* out = (float*)d_out;

    cudaFuncSetAttribute(gemm_f16, cudaFuncAttributeMaxDynamicSharedMemorySize, GEMM_SMEM);

    conv_x<<<(int)(((size_t)M_TOT * HIDN) / (256 * 8)), 256>>>(X);
    transpose_w<<<dim3(64, 32), dim3(32, 8)>>>(Kw, Vw);
    gemm_f16<<<dim3(16, 128), 256, GEMM_SMEM>>>(Kb, Vb, RH);
    fixup_kernel<<<M_TOT * NHD / 256, 256>>>(X, Kw, Kb, RH);
    scan_kernel<<<BSZ * NHD, 32>>>();
    gather_kernel<<<M_TOT * NHD / 16, 256>>>(Bw, out);
}

// round 13
// speedup vs baseline: 3.5484x; 2.7846x over previous
#include <cuda_runtime.h>
#include <cuda_fp16.h>
#include <cuda_bf16.h>
#include <stdint.h>

#define BSZ   8
#define LEN   2048
#define HIDN  1024
#define NHD   16
#define HDIM  64
#define M_TOT (BSZ * LEN)
#define FIX_TAU 4e-3f
#define FIX_CAP (M_TOT * NHD)

__device__ float  g_V1[(size_t)M_TOT * (NHD * HDIM)];
__device__ __half g_Xh[(size_t)M_TOT * HIDN];
__device__ __half g_WTh[(size_t)2048 * HIDN];   // [n][k] fp16 transposed weights
__device__ float  g_KTf[(size_t)1024 * HIDN];   // [n][k] fp32 transposed K weights
__device__ float  g_dots[M_TOT * NHD];
__device__ int2   g_fmap[M_TOT * NHD];
__device__ int2   g_bmap[M_TOT * NHD];
__device__ int    g_fix_cnt;
__device__ int    g_fix_ids[FIX_CAP];

// ---------------- helpers ----------------
__device__ __forceinline__ uint32_t smem_u32(const void* p) {
    return (uint32_t)__cvta_generic_to_shared(p);
}
__device__ __forceinline__ void cp_async16(uint32_t saddr, const void* gptr) {
    asm volatile("cp.async.ca.shared.global [%0], [%1], 16;\n" :: "r"(saddr), "l"(gptr));
}
__device__ __forceinline__ void cp_commit() { asm volatile("cp.async.commit_group;\n"); }
__device__ __forceinline__ void cp_wait1() { asm volatile("cp.async.wait_group 1;\n"); }

__device__ __forceinline__ void ldsm4(uint32_t* r, uint32_t addr) {
    asm volatile("ldmatrix.sync.aligned.m8n8.x4.shared.b16 {%0,%1,%2,%3}, [%4];"
        : "=r"(r[0]), "=r"(r[1]), "=r"(r[2]), "=r"(r[3]) : "r"(addr));
}
__device__ __forceinline__ void mma_f16(float* d, const uint32_t* a, const uint32_t* b) {
    asm volatile("mma.sync.aligned.m16n8k16.row.col.f32.f16.f16.f32 "
        "{%0,%1,%2,%3},{%4,%5,%6,%7},{%8,%9},{%0,%1,%2,%3};\n"
        : "+f"(d[0]), "+f"(d[1]), "+f"(d[2]), "+f"(d[3])
        : "r"(a[0]), "r"(a[1]), "r"(a[2]), "r"(a[3]), "r"(b[0]), "r"(b[1]));
}
// Neumaier compensated accumulate (branchless)
__device__ __forceinline__ void acc2(float& s, float& c, float v) {
    float t = s + v;
    float e1 = (s - t) + v;
    float e2 = (v - t) + s;
    c += (fabsf(s) >= fabsf(v)) ? e1 : e2;
    s = t;
}

// ---------------- init ----------------
__global__ void init_cnt() { g_fix_cnt = 0; }

// ---------------- pre-pass: X -> fp16 ----------------
__global__ __launch_bounds__(256) void conv_x(const float* __restrict__ X)
{
    size_t i = ((size_t)blockIdx.x * 256 + threadIdx.x) * 8;
    float4 v0 = *(const float4*)(X + i);
    float4 v1 = *(const float4*)(X + i + 4);
    __half2 h0 = __floats2half2_rn(v0.x, v0.y);
    __half2 h1 = __floats2half2_rn(v0.z, v0.w);
    __half2 h2 = __floats2half2_rn(v1.x, v1.y);
    __half2 h3 = __floats2half2_rn(v1.z, v1.w);
    uint4 o;
    o.x = *(uint32_t*)&h0; o.y = *(uint32_t*)&h1;
    o.z = *(uint32_t*)&h2; o.w = *(uint32_t*)&h3;
    *(uint4*)(g_Xh + i) = o;
}

// ---------------- pre-pass: W transpose -> fp16 [n][k] (+ fp32 for K half) ----
__global__ __launch_bounds__(256) void transpose_w(
    const float* __restrict__ Kw, const float* __restrict__ Vw)
{
    __shared__ float t[32][33];
    const int n0 = blockIdx.x * 32, k0 = blockIdx.y * 32;
    const float* W = (n0 < 1024) ? Kw : Vw;
    const int nb = n0 & 1023;
    const int tx = threadIdx.x, ty = threadIdx.y;
    #pragma unroll
    for (int r = ty; r < 32; r += 8)
        t[r][tx] = W[(size_t)(k0 + r) * 1024 + nb + tx];
    __syncthreads();
    #pragma unroll
    for (int r = ty; r < 32; r += 8) {
        float v = t[tx][r];
        g_WTh[(size_t)(n0 + r) * 1024 + k0 + tx] = __float2half_rn(v);
        if (n0 < 1024)
            g_KTf[(size_t)(n0 + r) * 1024 + k0 + tx] = v;
    }
}

// ---------------- fp16 mma GEMM, fused relu + bias + K-dot epilogue ----------
#define AROW 80
#define TILE_B (128 * AROW)
#define STG 3
#define GEMM_SMEM (2 * STG * TILE_B)

__device__ __forceinline__ void load_tiles_f16(int m0, int n0, int kt, int st, uint32_t sb, int tid)
{
    const int kk = kt * 32;
    const uint32_t sA = sb + st * TILE_B;
    const uint32_t sB = sb + (STG + st) * TILE_B;
    #pragma unroll
    for (int i = 0; i < 2; i++) {
        int c = tid + i * 256, row = c >> 2, q = c & 3;
        cp_async16(sA + (uint32_t)(row * AROW + q * 16),
                   g_Xh + (size_t)(m0 + row) * 1024 + kk + q * 8);
    }
    #pragma unroll
    for (int i = 0; i < 2; i++) {
        int c = tid + i * 256, row = c >> 2, q = c & 3;
        cp_async16(sB + (uint32_t)(row * AROW + q * 16),
                   g_WTh + (size_t)(n0 + row) * 1024 + kk + q * 8);
    }
}

__global__ __launch_bounds__(256) void gemm_f16(
    const float* __restrict__ Kb, const float* __restrict__ Vb,
    const float* __restrict__ RH)
{
    extern __shared__ char smem[];
    const uint32_t sb = smem_u32(smem);
    const int tid = threadIdx.x, wid = tid >> 5, lane = tid & 31;
    const int wm = wid & 3, wn = wid >> 2;
    const int m0 = blockIdx.y * 128;
    const int j0 = blockIdx.x * 128;
    const int n0 = j0;

    float acc[2][8][4];
    #pragma unroll
    for (int a = 0; a < 2; a++)
        #pragma unroll
        for (int b = 0; b < 8; b++)
            #pragma unroll
            for (int c = 0; c < 4; c++) acc[a][b][c] = 0.f;

    load_tiles_f16(m0, n0, 0, 0, sb, tid); cp_commit();
    load_tiles_f16(m0, n0, 1, 1, sb, tid); cp_commit();

    const int j = lane >> 3, r = lane & 7;
    const int KT = 32;
    for (int kt = 0; kt < KT; kt++) {
        cp_wait1();
        __syncthreads();
        if (kt + 2 < KT) load_tiles_f16(m0, n0, kt + 2, (kt + 2) % STG, sb, tid);
        cp_commit();

        const int st = kt % STG;
        const uint32_t sA = sb + st * TILE_B;
        const uint32_t sB = sb + (STG + st) * TILE_B;
        #pragma unroll
        for (int kh = 0; kh < 2; kh++) {
            uint32_t a0[4], a1[4];
            const uint32_t arow = (uint32_t)(wm * 32 + ((j & 1) << 3) + r);
            const uint32_t acol = (uint32_t)((kh << 4) + ((j >> 1) << 3));
            ldsm4(a0, sA + arow * AROW + acol * 2);
            ldsm4(a1, sA + (arow + 16) * AROW + acol * 2);
            #pragma unroll
            for (int g2 = 0; g2 < 4; g2++) {
                uint32_t bm[4];
                const uint32_t brow = (uint32_t)(wn * 64 + (g2 << 4) + ((j >> 1) << 3) + r);
                const uint32_t bcol = (uint32_t)((kh << 4) + ((j & 1) << 3));
                ldsm4(bm, sB + brow * AROW + bcol * 2);
                mma_f16(acc[0][2 * g2],     a0, &bm[0]);
                mma_f16(acc[1][2 * g2],     a1, &bm[0]);
                mma_f16(acc[0][2 * g2 + 1], a0, &bm[2]);
                mma_f16(acc[1][2 * g2 + 1], a1, &bm[2]);
            }
        }
    }

    const int g = lane >> 2, tg = lane & 3;
    if (j0 < 1024) {
        const int head = (j0 >> 6) + wn;
        const float* rh = RH + head * HDIM;
        float dotp[4] = {0.f, 0.f, 0.f, 0.f};
        #pragma unroll
        for (int mt = 0; mt < 2; mt++) {
            #pragma unroll
            for (int nt = 0; nt < 8; nt++) {
                int ch = nt * 8 + 2 * tg;
                int jc = j0 + wn * 64 + ch;
                float b0 = Kb[jc], b1 = Kb[jc + 1];
                float w0 = rh[ch], w1 = rh[ch + 1];
                float v;
                v = fmaxf(acc[mt][nt][0] + b0, 0.f); dotp[mt * 2 + 0] += v * w0;
                v = fmaxf(acc[mt][nt][1] + b1, 0.f); dotp[mt * 2 + 0] += v * w1;
                v = fmaxf(acc[mt][nt][2] + b0, 0.f); dotp[mt * 2 + 1] += v * w0;
                v = fmaxf(acc[mt][nt][3] + b1, 0.f); dotp[mt * 2 + 1] += v * w1;
            }
        }
        #pragma unroll
        for (int i = 0; i < 4; i++) {
            dotp[i] += __shfl_xor_sync(0xffffffffu, dotp[i], 1);
            dotp[i] += __shfl_xor_sync(0xffffffffu, dotp[i], 2);
        }
        if (tg == 0) {
            #pragma unroll
            for (int mt = 0; mt < 2; mt++) {
                int rr = m0 + wm * 32 + mt * 16 + g;
                float d0 = dotp[mt * 2 + 0], d1 = dotp[mt * 2 + 1];
                int id0 = rr * NHD + head, id1 = (rr + 8) * NHD + head;
                g_dots[id0] = d0;
                g_dots[id1] = d1;
                if (fabsf(d0 - 0.5f) < FIX_TAU) g_fix_ids[atomicAdd(&g_fix_cnt, 1)] = id0;
                if (fabsf(d1 - 0.5f) < FIX_TAU) g_fix_ids[atomicAdd(&g_fix_cnt, 1)] = id1;
            }
        }
    } else {
        #pragma unroll
        for (int mt = 0; mt < 2; mt++) {
            #pragma unroll
            for (int nt = 0; nt < 8; nt++) {
                int jv = (j0 - 1024) + wn * 64 + nt * 8 + 2 * tg;
                float b0 = Vb[jv], b1 = Vb[jv + 1];
                int rr = m0 + wm * 32 + mt * 16 + g;
                float2 s0, s1;
                s0.x = fmaxf(acc[mt][nt][0] + b0, 0.f);
                s0.y = fmaxf(acc[mt][nt][1] + b1, 0.f);
                s1.x = fmaxf(acc[mt][nt][2] + b0, 0.f);
                s1.y = fmaxf(acc[mt][nt][3] + b1, 0.f);
                *(float2*)&g_V1[(size_t)rr * 1024 + jv] = s0;
                *(float2*)&g_V1[(size_t)(rr + 8) * 1024 + jv] = s1;
            }
        }
    }
}

// ---------------- compensated-fp32 fixup of near-threshold dots -------------
// One block per candidate (grid-strided). Warp w handles head-channels
// h = w*8 .. w*8+7, lanes stream k coalesced; Dot2 (twoProd+Neumaier) per row.
__global__ __launch_bounds__(256) void fixup2(
    const float* __restrict__ X, const float* __restrict__ Kb,
    const float* __restrict__ RH)
{
    __shared__ float s_s[8], s_c[8];
    const int tid = threadIdx.x, wid = tid >> 5, lane = tid & 31;
    int cnt = g_fix_cnt;
    if (cnt > FIX_CAP) cnt = FIX_CAP;

    for (int i = blockIdx.x; i < cnt; i += gridDim.x) {
        const int t = g_fix_ids[i];
        const int m = t >> 4, n = t & 15;
        const float* xr = X + ((size_t)m << 10);

        float ws = 0.f, wc = 0.f;     // per-warp compensated dot over its 8 rows
        #pragma unroll
        for (int hs = 0; hs < 8; hs++) {
            const int h = wid * 8 + hs;
            const float* wrow = g_KTf + ((size_t)(n * 64 + h) << 10);
            float s = 0.f, c = 0.f;
            #pragma unroll 4
            for (int it = 0; it < 32; it++) {
                int k = it * 32 + lane;
                float a = xr[k], w = wrow[k];
                float p = a * w;
                float e = fmaf(a, w, -p);
                acc2(s, c, p);
                c += e;
            }
            // warp reduce (s,c)
            #pragma unroll
            for (int off = 16; off > 0; off >>= 1) {
                float s2 = __shfl_down_sync(0xffffffffu, s, off);
                float c2 = __shfl_down_sync(0xffffffffu, c, off);
                acc2(s, c, s2);
                c += c2;
            }
            if (lane == 0) {
                float pre = s + c + Kb[n * 64 + h];
                float rv = fmaxf(pre, 0.f) * RH[n * 64 + h];
                acc2(ws, wc, rv);
            }
        }
        if (lane == 0) { s_s[wid] = ws; s_c[wid] = wc; }
        __syncthreads();
        if (tid == 0) {
            float s = 0.f, c = 0.f;
            #pragma unroll
            for (int w2 = 0; w2 < 8; w2++) { acc2(s, c, s_s[w2]); c += s_c[w2]; }
            g_dots[t] = s + c;
        }
        __syncthreads();
    }
}

// ---------------- warp-segmented nearest-valid scan ----------------
struct Seg { int cnt, v1, v2; };

__device__ __forceinline__ Seg seg_combine(const Seg& prev, const Seg& cur) {
    Seg r;
    if (cur.cnt >= 2) r = cur;
    else if (cur.cnt == 1) { r.cnt = min(prev.cnt + 1, 2); r.v1 = cur.v1; r.v2 = prev.v1; }
    else r = prev;
    return r;
}

__global__ void scan_kernel()
{
    const int bidx = blockIdx.x >> 4;
    const int n = blockIdx.x & 15;
    const int lane = threadIdx.x;
    const int base_l = lane * 64;

    const float* dp = g_dots + ((size_t)bidx * LEN) * NHD + n;
    unsigned long long bits = 0ull;
    for (int j = 0; j < 64; j++)
        if (__ldg(&dp[(size_t)(base_l + j) * NHD]) > 0.5f) bits |= (1ull << j);

    { // forward: ignore pos 0, defaults 0
        unsigned long long fb = bits;
        if (lane == 0) fb &= ~1ull;
        Seg s; s.cnt = 0; s.v1 = 0; s.v2 = 0;
        for (int j = 0; j < 64; j++)
            if ((fb >> j) & 1ull) { s.v2 = s.v1; s.v1 = base_l + j; s.cnt = min(s.cnt + 1, 2); }
        Seg inc = s;
        for (int d = 1; d < 32; d <<= 1) {
            Seg o;
            o.cnt = __shfl_up_sync(0xffffffffu, inc.cnt, d);
            o.v1  = __shfl_up_sync(0xffffffffu, inc.v1, d);
            o.v2  = __shfl_up_sync(0xffffffffu, inc.v2, d);
            if (lane >= d) inc = seg_combine(o, inc);
        }
        Seg ex;
        ex.cnt = __shfl_up_sync(0xffffffffu, inc.cnt, 1);
        ex.v1  = __shfl_up_sync(0xffffffffu, inc.v1, 1);
        ex.v2  = __shfl_up_sync(0xffffffffu, inc.v2, 1);
        if (lane == 0) { ex.cnt = 0; ex.v1 = 0; ex.v2 = 0; }
        int a = (ex.cnt >= 1) ? ex.v1 : 0;
        int b = (ex.cnt >= 2) ? ex.v2 : 0;
        int2* out = g_fmap + ((size_t)bidx * LEN) * NHD + n;
        for (int j = 0; j < 64; j++) {
            int p = base_l + j;
            if ((fb >> j) & 1ull) { b = a; a = p; }
            out[(size_t)p * NHD] = make_int2(a, b);
        }
    }

    { // backward: ignore pos L-1, store mirrored index, defaults L-1
        unsigned long long bb = bits;
        if (lane == 31) bb &= ~(1ull << 63);
        Seg s; s.cnt = 0; s.v1 = LEN - 1; s.v2 = LEN - 1;
        for (int j = 63; j >= 0; j--)
            if ((bb >> j) & 1ull) { s.v2 = s.v1; s.v1 = (LEN - 1) - (base_l + j); s.cnt = min(s.cnt + 1, 2); }
        Seg inc = s;
        for (int d = 1; d < 32; d <<= 1) {
            Seg o;
            o.cnt = __shfl_down_sync(0xffffffffu, inc.cnt, d);
            o.v1  = __shfl_down_sync(0xffffffffu, inc.v1, d);
            o.v2  = __shfl_down_sync(0xffffffffu, inc.v2, d);
            if (lane + d < 32) inc = seg_combine(o, inc);
        }
        Seg ex;
        ex.cnt = __shfl_down_sync(0xffffffffu, inc.cnt, 1);
        ex.v1  = __shfl_down_sync(0xffffffffu, inc.v1, 1);
        ex.v2  = __shfl_down_sync(0xffffffffu, inc.v2, 1);
        if (lane == 31) { ex.cnt = 0; ex.v1 = LEN - 1; ex.v2 = LEN - 1; }
        int a = (ex.cnt >= 1) ? ex.v1 : (LEN - 1);
        int b = (ex.cnt >= 2) ? ex.v2 : (LEN - 1);
        int2* out = g_bmap + ((size_t)bidx * LEN) * NHD + n;
        for (int j = 63; j >= 0; j--) {
            int p = base_l + j;
            if ((bb >> j) & 1ull) { b = a; a = (LEN - 1) - p; }
            out[(size_t)p * NHD] = make_int2(a, b);
        }
    }
}

// ---------------- weighted gather ----------------
__global__ __launch_bounds__(256) void gather_kernel(
    const float* __restrict__ Bw, float* __restrict__ out)
{
    int gid = blockIdx.x * 16 + (threadIdx.x >> 4);
    int q = threadIdx.x & 15;
    int n = gid & 15;
    int bl = gid >> 4;
    int b = bl >> 11;
    int2 fm = g_fmap[(size_t)bl * NHD + n];
    int2 bm = g_bmap[(size_t)bl * NHD + n];
    const float* vbase = g_V1 + (((size_t)b << 11) << 10);
    size_t coff = (size_t)n * 64 + q * 4;
    float4 v0 = *(const float4*)(vbase + ((size_t)fm.x << 10) + coff);
    float4 v1 = *(const float4*)(vbase + ((size_t)fm.y << 10) + coff);
    float4 v2 = *(const float4*)(vbase + ((size_t)bm.x << 10) + coff);
    float4 v3 = *(const float4*)(vbase + ((size_t)bm.y << 10) + coff);
    float w0 = Bw[n * 4 + 0], w1 = Bw[n * 4 + 1], w2 = Bw[n * 4 + 2], w3 = Bw[n * 4 + 3];
    float4 r;
    r.x = w0 * v0.x + w1 * v1.x + w2 * v2.x + w3 * v3.x;
    r.y = w0 * v0.y + w1 * v1.y + w2 * v2.y + w3 * v3.y;
    r.z = w0 * v0.z + w1 * v1.z + w2 * v2.z + w3 * v3.z;
    r.w = w0 * v0.w + w1 * v1.w + w2 * v2.w + w3 * v3.w;
    *(float4*)(out + (size_t)bl * 1024 + coff) = r;
}

// ---------------- launch ----------------
extern "C" void kernel_launch(void* const* d_in, const int* in_sizes, int n_in,
                              void* d_out, int out_size)
{
    const float* X  = (const float*)d_in[0];
    const float* Kw = (const float*)d_in[1];
    const float* Kb = (const float*)d_in[2];
    const float* Vw = (const float*)d_in[3];
    const float* Vb = (const float*)d_in[4];
    const float* Bw = (const float*)d_in[5];
    const float* RH = (const float*)d_in[6];
    float* out = (float*)d_out;

    cudaFuncSetAttribute(gemm_f16, cudaFuncAttributeMaxDynamicSharedMemorySize, GEMM_SMEM);

    init_cnt<<<1, 1>>>();
    conv_x<<<(int)(((size_t)M_TOT * HIDN) / (256 * 8)), 256>>>(X);
    transpose_w<<<dim3(64, 32), dim3(32, 8)>>>(Kw, Vw);
    gemm_f16<<<dim3(16, 128), 256, GEMM_SMEM>>>(Kb, Vb, RH);
    fixup2<<<512, 256>>>(X, Kb, RH);
    scan_kernel<<<BSZ * NHD, 32>>>();
    gather_kernel<<<M_TOT * NHD / 16, 256>>>(Bw, out);
}